// round 2
// baseline (speedup 1.0000x reference)
#include <cuda_runtime.h>
#include <cstdint>

// ---------------------------------------------------------------------------
// C[8192,4096] = A[8192,4096] * W[4096,4096]^T  (fp32 in/out)
// Harness compiles PTX with .target sm_103 (no 'a') -> tcgen05 unavailable.
// Path: prepass rounds A,W to tf32 (cvt.rna) into device scratch; GEMM uses
// mma.sync.m16n8k8 tf32 with a 3-stage cp.async pipeline.
// BM=128, BN=128, BK=32, 256 threads (8 warps, 4x2), warp tile 32x64.
// ---------------------------------------------------------------------------

#define MTOT 8192
#define KDIM 4096
#define NDIM 4096

#define BM 128
#define BN 128
#define BK 32
#define KITERS (KDIM / BK)        // 128
#define STAGES 3

#define LDSS 36                    // padded row stride in words (32 + 4)
#define STAGE_WORDS ((BM + BN) * LDSS)          // 9216 words = 36864 B
#define SMEM_TOTAL (STAGES * STAGE_WORDS * 4)   // 110592 B

// tf32-rounded scratch copies (device globals: allowed, no allocation)
__device__ float g_A[(size_t)MTOT * KDIM];
__device__ float g_W[(size_t)NDIM * KDIM];

// ------------------------------- helpers -----------------------------------

__device__ __forceinline__ uint32_t smem_u32(const void* p) {
    uint32_t a;
    asm("{ .reg .u64 t; cvta.to.shared.u64 t, %1; cvt.u32.u64 %0, t; }"
        : "=r"(a) : "l"(p));
    return a;
}

__device__ __forceinline__ float tf32_round(float x) {
    uint32_t u;
    asm("cvt.rna.tf32.f32 %0, %1;" : "=r"(u) : "f"(x));
    return __uint_as_float(u);
}

__device__ __forceinline__ void cp_async16(uint32_t dst, const void* src) {
    asm volatile("cp.async.cg.shared.global [%0], [%1], 16;\n"
                 :: "r"(dst), "l"(src) : "memory");
}
__device__ __forceinline__ void cp_commit() {
    asm volatile("cp.async.commit_group;\n" ::: "memory");
}
__device__ __forceinline__ void cp_wait1() {
    asm volatile("cp.async.wait_group 1;\n" ::: "memory");
}

__device__ __forceinline__ void mma_m16n8k8(float* c, const uint32_t* a,
                                            const uint32_t* b) {
    asm volatile(
        "mma.sync.aligned.m16n8k8.row.col.f32.tf32.tf32.f32 "
        "{%0,%1,%2,%3}, {%4,%5,%6,%7}, {%8,%9}, {%0,%1,%2,%3};"
        : "+f"(c[0]), "+f"(c[1]), "+f"(c[2]), "+f"(c[3])
        : "r"(a[0]), "r"(a[1]), "r"(a[2]), "r"(a[3]),
          "r"(b[0]), "r"(b[1]));
}

// ------------------------------- prepass ------------------------------------
// Round A and W to tf32 (round-to-nearest-with-ties-away removes the ~1e-3
// truncation bias the HW-implicit conversion would add).

__global__ void __launch_bounds__(256) prepass_kernel(const float* __restrict__ A,
                                                      const float* __restrict__ W) {
    const long long nA = (long long)MTOT * KDIM / 4;
    const long long nW = (long long)NDIM * KDIM / 4;
    const long long stride = (long long)gridDim.x * blockDim.x;
    for (long long i = (long long)blockIdx.x * blockDim.x + threadIdx.x;
         i < nA + nW; i += stride) {
        const float4* src;
        float4* dst;
        long long j;
        if (i < nA) { src = (const float4*)A; dst = (float4*)g_A; j = i; }
        else        { src = (const float4*)W; dst = (float4*)g_W; j = i - nA; }
        float4 v = src[j];
        v.x = tf32_round(v.x);
        v.y = tf32_round(v.y);
        v.z = tf32_round(v.z);
        v.w = tf32_round(v.w);
        dst[j] = v;
    }
}

// ------------------------------- GEMM ---------------------------------------

__global__ void __launch_bounds__(256, 2) gemm_kernel(float* __restrict__ out) {
    extern __shared__ float smem[];
    const int tid = threadIdx.x;
    const int lane = tid & 31;
    const int wid = tid >> 5;
    const int warp_m = wid & 3;       // 0..3 -> 32-row strip
    const int warp_n = wid >> 2;      // 0..1 -> 64-col strip
    const int grp = lane >> 2;        // groupID (0..7)
    const int tig = lane & 3;         // threadID-in-group (0..3)

    const int m_base = blockIdx.y * BM;
    const int n_base = blockIdx.x * BN;

    const float* Abase = g_A + (size_t)m_base * KDIM;
    const float* Bbase = g_W + (size_t)n_base * KDIM;

    // producer geometry: 1024 16B-chunks per matrix per stage, 4 per thread
    const int prow = tid >> 3;        // 0..31
    const int pcc = tid & 7;          // 16B chunk within 128B of K

    float acc[2][8][4];
    #pragma unroll
    for (int t = 0; t < 2; t++)
        #pragma unroll
        for (int j = 0; j < 8; j++)
            #pragma unroll
            for (int q = 0; q < 4; q++)
                acc[t][j][q] = 0.0f;

    auto produce = [&](int stage, int kb) {
        float* As = smem + stage * STAGE_WORDS;
        float* Bs = As + BM * LDSS;
        const float* Ag = Abase + (size_t)prow * KDIM + kb * BK + pcc * 4;
        const float* Bg = Bbase + (size_t)prow * KDIM + kb * BK + pcc * 4;
        #pragma unroll
        for (int j = 0; j < 4; j++) {
            cp_async16(smem_u32(As + (prow + 32 * j) * LDSS + pcc * 4),
                       Ag + (size_t)(32 * j) * KDIM);
            cp_async16(smem_u32(Bs + (prow + 32 * j) * LDSS + pcc * 4),
                       Bg + (size_t)(32 * j) * KDIM);
        }
    };

    // prologue: fill 2 of 3 stages
    produce(0, 0); cp_commit();
    produce(1, 1); cp_commit();

    int stage = 0;
    for (int it = 0; it < KITERS; ++it) {
        cp_wait1();          // stage `it` fully resident
        __syncthreads();     // all threads see it; stage (it+2)%3 is reusable

        if (it + 2 < KITERS) {
            int ps = stage + 2; if (ps >= STAGES) ps -= STAGES;
            produce(ps, it + 2);
        }
        cp_commit();         // keep group count fixed (possibly empty group)

        const uint32_t* Au = (const uint32_t*)(smem + stage * STAGE_WORDS);
        const uint32_t* Bu = Au + BM * LDSS;

        #pragma unroll
        for (int ks = 0; ks < 4; ks++) {
            const int k0 = ks * 8 + tig;
            uint32_t a[2][4], b[8][2];
            #pragma unroll
            for (int t = 0; t < 2; t++) {
                const int r = warp_m * 32 + t * 16 + grp;
                a[t][0] = Au[r * LDSS + k0];
                a[t][1] = Au[(r + 8) * LDSS + k0];
                a[t][2] = Au[r * LDSS + k0 + 4];
                a[t][3] = Au[(r + 8) * LDSS + k0 + 4];
            }
            #pragma unroll
            for (int j = 0; j < 8; j++) {
                const int n = warp_n * 64 + j * 8 + grp;
                b[j][0] = Bu[n * LDSS + k0];
                b[j][1] = Bu[n * LDSS + k0 + 4];
            }
            #pragma unroll
            for (int t = 0; t < 2; t++)
                #pragma unroll
                for (int j = 0; j < 8; j++)
                    mma_m16n8k8(acc[t][j], a[t], b[j]);
        }

        if (++stage == STAGES) stage = 0;
    }

    // epilogue: float2 stores, 32B-sector aligned
    #pragma unroll
    for (int t = 0; t < 2; t++) {
        const int r0 = m_base + warp_m * 32 + t * 16 + grp;
        #pragma unroll
        for (int j = 0; j < 8; j++) {
            const int cg = n_base + warp_n * 64 + j * 8 + 2 * tig;
            float2 v0 = make_float2(acc[t][j][0], acc[t][j][1]);
            float2 v1 = make_float2(acc[t][j][2], acc[t][j][3]);
            *reinterpret_cast<float2*>(out + (size_t)r0 * NDIM + cg) = v0;
            *reinterpret_cast<float2*>(out + (size_t)(r0 + 8) * NDIM + cg) = v1;
        }
    }
}

// ------------------------------- launch --------------------------------------

extern "C" void kernel_launch(void* const* d_in, const int* in_sizes, int n_in,
                              void* d_out, int out_size) {
    const float* A = (const float*)d_in[0];   // [8,1024,4096] == [8192,4096]
    const float* W = (const float*)d_in[1];   // [4096,4096] (N,K)
    float* out = (float*)d_out;               // [8192,4096]
    (void)in_sizes; (void)n_in; (void)out_size;

    cudaFuncSetAttribute(gemm_kernel,
                         cudaFuncAttributeMaxDynamicSharedMemorySize, SMEM_TOTAL);

    prepass_kernel<<<1184, 256>>>(A, W);

    dim3 grid(NDIM / BN, MTOT / BM);   // (32, 64) = 2048 CTAs
    gemm_kernel<<<grid, 256, SMEM_TOTAL>>>(out);
}

// round 3
// speedup vs baseline: 1.0178x; 1.0178x over previous
#include <cuda_runtime.h>
#include <cstdint>

// ---------------------------------------------------------------------------
// C[8192,4096] = A[8192,4096] * W[4096,4096]^T  (fp32 in/out)
// tf32 mma.sync.m16n8k8 path (harness targets sm_103 base ISA; no tcgen05).
// R3: BM=256, BN=128, BK=32, 256 threads, warp tile 64x64 (4x2 warps),
// 4-stage cp.async pipeline (wait_group 2), prepass rounds inputs to tf32.
// ---------------------------------------------------------------------------

#define MTOT 8192
#define KDIM 4096
#define NDIM 4096

#define BM 256
#define BN 128
#define BK 32
#define KITERS (KDIM / BK)        // 128
#define STAGES 4

#define LDSS 36                    // padded row stride in words (32 + 4)
#define STAGE_WORDS ((BM + BN) * LDSS)          // 13824 words = 55296 B
#define SMEM_TOTAL (STAGES * STAGE_WORDS * 4)   // 221184 B

// tf32-rounded scratch copies (device globals: allowed, no allocation)
__device__ float g_A[(size_t)MTOT * KDIM];
__device__ float g_W[(size_t)NDIM * KDIM];

// ------------------------------- helpers -----------------------------------

__device__ __forceinline__ uint32_t smem_u32(const void* p) {
    uint32_t a;
    asm("{ .reg .u64 t; cvta.to.shared.u64 t, %1; cvt.u32.u64 %0, t; }"
        : "=r"(a) : "l"(p));
    return a;
}

__device__ __forceinline__ float tf32_round(float x) {
    uint32_t u;
    asm("cvt.rna.tf32.f32 %0, %1;" : "=r"(u) : "f"(x));
    return __uint_as_float(u);
}

__device__ __forceinline__ void cp_async16(uint32_t dst, const void* src) {
    asm volatile("cp.async.cg.shared.global [%0], [%1], 16;\n"
                 :: "r"(dst), "l"(src) : "memory");
}
__device__ __forceinline__ void cp_commit() {
    asm volatile("cp.async.commit_group;\n" ::: "memory");
}
__device__ __forceinline__ void cp_wait2() {
    asm volatile("cp.async.wait_group 2;\n" ::: "memory");
}

__device__ __forceinline__ void mma_m16n8k8(float* c, const uint32_t* a,
                                            const uint32_t* b) {
    asm volatile(
        "mma.sync.aligned.m16n8k8.row.col.f32.tf32.tf32.f32 "
        "{%0,%1,%2,%3}, {%4,%5,%6,%7}, {%8,%9}, {%0,%1,%2,%3};"
        : "+f"(c[0]), "+f"(c[1]), "+f"(c[2]), "+f"(c[3])
        : "r"(a[0]), "r"(a[1]), "r"(a[2]), "r"(a[3]),
          "r"(b[0]), "r"(b[1]));
}

// ------------------------------- prepass ------------------------------------
// Round A and W to tf32 (round-to-nearest removes the ~1e-3 truncation bias
// the HW-implicit conversion would add).

__global__ void __launch_bounds__(256) prepass_kernel(const float* __restrict__ A,
                                                      const float* __restrict__ W) {
    const long long nA = (long long)MTOT * KDIM / 4;
    const long long nW = (long long)NDIM * KDIM / 4;
    const long long stride = (long long)gridDim.x * blockDim.x;
    for (long long i = (long long)blockIdx.x * blockDim.x + threadIdx.x;
         i < nA + nW; i += stride) {
        const float4* src;
        float4* dst;
        long long j;
        if (i < nA) { src = (const float4*)A; dst = (float4*)g_A; j = i; }
        else        { src = (const float4*)W; dst = (float4*)g_W; j = i - nA; }
        float4 v = src[j];
        v.x = tf32_round(v.x);
        v.y = tf32_round(v.y);
        v.z = tf32_round(v.z);
        v.w = tf32_round(v.w);
        dst[j] = v;
    }
}

// ------------------------------- GEMM ---------------------------------------

__global__ void __launch_bounds__(256, 1) gemm_kernel(float* __restrict__ out) {
    extern __shared__ float smem[];
    const int tid = threadIdx.x;
    const int lane = tid & 31;
    const int wid = tid >> 5;
    const int warp_m = wid & 3;       // 0..3 -> 64-row strip
    const int warp_n = wid >> 2;      // 0..1 -> 64-col strip
    const int grp = lane >> 2;        // groupID (0..7)
    const int tig = lane & 3;         // threadID-in-group (0..3)

    const int m_base = blockIdx.y * BM;
    const int n_base = blockIdx.x * BN;

    const float* Abase = g_A + (size_t)m_base * KDIM;
    const float* Bbase = g_W + (size_t)n_base * KDIM;

    // producer geometry: A = 2048 16B-chunks/stage, B = 1024 -> 12 per thread
    const int prow = tid >> 3;        // 0..31
    const int pcc = tid & 7;          // 16B chunk within 128B of K

    float acc[4][8][4];
    #pragma unroll
    for (int t = 0; t < 4; t++)
        #pragma unroll
        for (int j = 0; j < 8; j++)
            #pragma unroll
            for (int q = 0; q < 4; q++)
                acc[t][j][q] = 0.0f;

    auto produce = [&](int stage, int kb) {
        float* As = smem + stage * STAGE_WORDS;
        float* Bs = As + BM * LDSS;
        const float* Ag = Abase + (size_t)prow * KDIM + kb * BK + pcc * 4;
        const float* Bg = Bbase + (size_t)prow * KDIM + kb * BK + pcc * 4;
        #pragma unroll
        for (int j = 0; j < 8; j++)
            cp_async16(smem_u32(As + (prow + 32 * j) * LDSS + pcc * 4),
                       Ag + (size_t)(32 * j) * KDIM);
        #pragma unroll
        for (int j = 0; j < 4; j++)
            cp_async16(smem_u32(Bs + (prow + 32 * j) * LDSS + pcc * 4),
                       Bg + (size_t)(32 * j) * KDIM);
    };

    // prologue: fill 3 of 4 stages
    produce(0, 0); cp_commit();
    produce(1, 1); cp_commit();
    produce(2, 2); cp_commit();

    for (int it = 0; it < KITERS; ++it) {
        const int stage = it & 3;

        cp_wait2();          // stage `it` fully resident (<=2 groups pending)
        __syncthreads();     // all reads of stage it-1 are done; safe to refill

        if (it + 3 < KITERS) produce((it + 3) & 3, it + 3);
        cp_commit();         // fixed group count per iteration

        const uint32_t* Au = (const uint32_t*)(smem + stage * STAGE_WORDS);
        const uint32_t* Bu = Au + BM * LDSS;

        #pragma unroll
        for (int ks = 0; ks < 4; ks++) {
            const int k0 = ks * 8 + tig;
            uint32_t a[4][4], b[8][2];
            #pragma unroll
            for (int t = 0; t < 4; t++) {
                const int r = warp_m * 64 + t * 16 + grp;
                a[t][0] = Au[r * LDSS + k0];
                a[t][1] = Au[(r + 8) * LDSS + k0];
                a[t][2] = Au[r * LDSS + k0 + 4];
                a[t][3] = Au[(r + 8) * LDSS + k0 + 4];
            }
            #pragma unroll
            for (int j = 0; j < 8; j++) {
                const int n = warp_n * 64 + j * 8 + grp;
                b[j][0] = Bu[n * LDSS + k0];
                b[j][1] = Bu[n * LDSS + k0 + 4];
            }
            #pragma unroll
            for (int t = 0; t < 4; t++)
                #pragma unroll
                for (int j = 0; j < 8; j++)
                    mma_m16n8k8(acc[t][j], a[t], b[j]);
        }
    }

    // epilogue: float2 stores, 32B-sector aligned
    #pragma unroll
    for (int t = 0; t < 4; t++) {
        const int r0 = m_base + warp_m * 64 + t * 16 + grp;
        #pragma unroll
        for (int j = 0; j < 8; j++) {
            const int cg = n_base + warp_n * 64 + j * 8 + 2 * tig;
            float2 v0 = make_float2(acc[t][j][0], acc[t][j][1]);
            float2 v1 = make_float2(acc[t][j][2], acc[t][j][3]);
            *reinterpret_cast<float2*>(out + (size_t)r0 * NDIM + cg) = v0;
            *reinterpret_cast<float2*>(out + (size_t)(r0 + 8) * NDIM + cg) = v1;
        }
    }
}

// ------------------------------- launch --------------------------------------

extern "C" void kernel_launch(void* const* d_in, const int* in_sizes, int n_in,
                              void* d_out, int out_size) {
    const float* A = (const float*)d_in[0];   // [8,1024,4096] == [8192,4096]
    const float* W = (const float*)d_in[1];   // [4096,4096] (N,K)
    float* out = (float*)d_out;               // [8192,4096]
    (void)in_sizes; (void)n_in; (void)out_size;

    cudaFuncSetAttribute(gemm_kernel,
                         cudaFuncAttributeMaxDynamicSharedMemorySize, SMEM_TOTAL);

    prepass_kernel<<<1184, 256>>>(A, W);

    dim3 grid(NDIM / BN, MTOT / BM);   // (32, 32) = 1024 CTAs
    gemm_kernel<<<grid, 256, SMEM_TOTAL>>>(out);
}